// round 14
// baseline (speedup 1.0000x reference)
#include <cuda_runtime.h>
#include <cstdint>

// ---------------- problem constants (from reference) ----------------
#define FH    32
#define FW    88
#define NCAM  6
#define ND    118
#define NC    80
#define NXX   360
#define NYY   360
#define NPTS  (NCAM*ND*FH*FW)      // 1,993,728
#define NCELL (NXX*NYY)            // 129,600
#define PT_PER_CAM (ND*FH*FW)
#define PT_PER_D   (FH*FW)
#define NBLK1 507                  // ceil(NCELL/256)
#define NQ    20                   // NC/4 float4 quads per point row

// ---------------- device scratch (static: no allocation) ----------------
__device__ int   g_lin[NPTS];
__device__ int   g_cnt[NCELL];
__device__ int   g_off[NCELL];
__device__ int   g_cur[NCELL];
__device__ int   g_blk[512];
__device__ int   g_idx[NPTS];
// per-camera: [0:9) invPostRot [9:12) post_trans [12:21) G = E*rots*invK [21:24) E*trans+ET
__device__ float g_cam[NCAM][24];

// ---------------- exact-fp32 helpers (no FMA contraction) — FROZEN numerics ----------------
__device__ __forceinline__ float dot3(const float* m, float a, float b, float c) {
    return __fadd_rn(__fadd_rn(__fmul_rn(m[0], a), __fmul_rn(m[1], b)),
                     __fmul_rn(m[2], c));
}

__device__ __forceinline__ void inv3(const float m[9], float out[9]) {
    float a=m[0],b=m[1],c=m[2],d=m[3],e=m[4],f=m[5],g=m[6],h=m[7],i=m[8];
    float A =  (e*i - f*h);
    float B = -(d*i - f*g);
    float C =  (d*h - e*g);
    float det = a*A + b*B + c*C;
    float id = 1.0f / det;
    out[0] =  A*id;            out[1] = -(b*i - c*h)*id;  out[2] =  (b*f - c*e)*id;
    out[3] =  B*id;            out[4] =  (a*i - c*g)*id;  out[5] = -(a*f - c*d)*id;
    out[6] =  C*id;            out[7] = -(a*h - b*g)*id;  out[8] =  (a*e - b*d)*id;
}

__device__ __forceinline__ void mm3(const float A[9], const float B[9], float C[9]) {
    #pragma unroll
    for (int i = 0; i < 3; i++)
        #pragma unroll
        for (int j = 0; j < 3; j++)
            C[i*3+j] = __fadd_rn(__fadd_rn(__fmul_rn(A[i*3+0], B[0*3+j]),
                                           __fmul_rn(A[i*3+1], B[1*3+j])),
                                 __fmul_rn(A[i*3+2], B[2*3+j]));
}

// ---------------- kernel 0: setup (block 0) + zero counters (all blocks) ----------------
__global__ void setup_zero_kernel(const float* __restrict__ c2l,
                                  const float* __restrict__ intr,
                                  const float* __restrict__ ida,
                                  const float* __restrict__ bda) {
    int gid = blockIdx.x * blockDim.x + threadIdx.x;
    if (gid < NCELL) g_cnt[gid] = 0;

    if (blockIdx.x == 0 && threadIdx.x < NCAM) {
        int n = threadIdx.x;
        const float* M = c2l + n*16;
        float rots[9]  = {M[0],M[1],M[2],  M[4],M[5],M[6],  M[8],M[9],M[10]};
        float trans[3] = {M[3], M[7], M[11]};

        const float* Ki = intr + n*16;
        float K[9] = {Ki[0],Ki[1],Ki[2], Ki[4],Ki[5],Ki[6], Ki[8],Ki[9],Ki[10]};

        const float* Ai = ida + n*16;
        float PR[9] = {Ai[0],Ai[1],Ai[2], Ai[4],Ai[5],Ai[6], Ai[8],Ai[9],Ai[10]};
        float PT[3] = {Ai[3], Ai[7], Ai[11]};

        float E[9]  = {bda[0],bda[1],bda[2], bda[4],bda[5],bda[6], bda[8],bda[9],bda[10]};
        float ET[3] = {bda[3], bda[7], bda[11]};

        float invK[9], invPR[9], cmb[9], G[9];
        inv3(K, invK);
        inv3(PR, invPR);
        mm3(rots, invK, cmb);   // combine = rots @ inv(intrins)
        mm3(E, cmb, G);         // identity E -> G == cmb bit-exactly

        float o[3];
        #pragma unroll
        for (int i = 0; i < 3; i++)
            o[i] = __fadd_rn(dot3(E + i*3, trans[0], trans[1], trans[2]), ET[i]);

        float* cp = g_cam[n];
        #pragma unroll
        for (int i = 0; i < 9; i++) cp[i]      = invPR[i];
        #pragma unroll
        for (int i = 0; i < 3; i++) cp[9 + i]  = PT[i];
        #pragma unroll
        for (int i = 0; i < 9; i++) cp[12 + i] = G[i];
        #pragma unroll
        for (int i = 0; i < 3; i++) cp[21 + i] = o[i];
    }
}

// ---------------- kernel 1: geometry -> voxel index + histogram (FROZEN numerics) ----------------
__global__ void geom_kernel(const int* __restrict__ depth_kept) {
    int p = blockIdx.x * blockDim.x + threadIdx.x;
    if (p >= NPTS) return;

    int n  = p / PT_PER_CAM;
    int r  = p - n * PT_PER_CAM;
    int d  = r / PT_PER_D;
    int r2 = r - d * PT_PER_D;
    int h  = r2 / FW;
    int w  = r2 - h * FW;

    const float* cp = g_cam[n];

    const float STEPX = 703.0f / 87.0f;
    const float STEPY = 255.0f / 31.0f;
    float fx = __fmul_rn((float)w, STEPX);
    float fy = __fmul_rn((float)h, STEPY);
    float fd = __fadd_rn(1.0f, __fmul_rn(0.5f, (float)d));

    float p0 = __fadd_rn(fx, -cp[9]);
    float p1 = __fadd_rn(fy, -cp[10]);
    float p2 = __fadd_rn(fd, -cp[11]);

    float q0 = dot3(cp + 0, p0, p1, p2);
    float q1 = dot3(cp + 3, p0, p1, p2);
    float q2 = dot3(cp + 6, p0, p1, p2);

    float r0 = __fmul_rn(q0, q2);
    float r1 = __fmul_rn(q1, q2);

    float px = __fadd_rn(dot3(cp + 12, r0, r1, q2), cp[21]);
    float py = __fadd_rn(dot3(cp + 15, r0, r1, q2), cp[22]);
    float pz = __fadd_rn(dot3(cp + 18, r0, r1, q2), cp[23]);

    // XLA lowers /DX (constant) to multiply-by-RN-reciprocal — decides the
    // exact-boundary slabs (cams 0/3). Confirmed by R13 pass; do not change.
    const float INV_DXY = 1.0f / 0.3f;
    const float INV_DZ  = 1.0f / 20.0f;
    int cx = (int)floorf(__fmul_rn(__fadd_rn(px, 54.0f), INV_DXY));
    int cy = (int)floorf(__fmul_rn(__fadd_rn(py, 54.0f), INV_DXY));
    int cz = (int)floorf(__fmul_rn(__fadd_rn(pz, 10.0f), INV_DZ));

    bool ok = (cx >= 0) & (cx < NXX) & (cy >= 0) & (cy < NYY) &
              (cz >= 0) & (cz < 1)   & (depth_kept[p] != 0);

    int lin = ok ? (cx * NYY + cy) : -1;
    g_lin[p] = lin;
    if (ok) atomicAdd(&g_cnt[lin], 1);
}

// ---------------- kernels 2a/2b/2c: exclusive prefix scan (warp shuffles) ----------------
__global__ void scan_a_kernel() {
    __shared__ int wsum[8];
    int gid  = blockIdx.x * 256 + threadIdx.x;
    int lane = threadIdx.x & 31, wid = threadIdx.x >> 5;
    int v = (gid < NCELL) ? g_cnt[gid] : 0;
    int s = v;
    #pragma unroll
    for (int dd = 1; dd < 32; dd <<= 1) {
        int t = __shfl_up_sync(0xFFFFFFFFu, s, dd);
        if (lane >= dd) s += t;
    }
    if (lane == 31) wsum[wid] = s;
    __syncthreads();
    if (wid == 0) {
        int ws = (lane < 8) ? wsum[lane] : 0;
        #pragma unroll
        for (int dd = 1; dd < 8; dd <<= 1) {
            int t = __shfl_up_sync(0xFFFFFFFFu, ws, dd);
            if (lane >= dd) ws += t;
        }
        if (lane < 8) wsum[lane] = ws;   // inclusive warp-prefix
    }
    __syncthreads();
    int base = wid ? wsum[wid - 1] : 0;
    if (gid < NCELL) g_off[gid] = base + s - v;
    if (threadIdx.x == 255) g_blk[blockIdx.x] = base + s;   // block total
}

__global__ void scan_b_kernel() {
    __shared__ int wsum[16];
    int lane = threadIdx.x & 31, wid = threadIdx.x >> 5;
    int v = (threadIdx.x < NBLK1) ? g_blk[threadIdx.x] : 0;
    int s = v;
    #pragma unroll
    for (int dd = 1; dd < 32; dd <<= 1) {
        int t = __shfl_up_sync(0xFFFFFFFFu, s, dd);
        if (lane >= dd) s += t;
    }
    if (lane == 31) wsum[wid] = s;
    __syncthreads();
    if (wid == 0) {
        int ws = (lane < 16) ? wsum[lane] : 0;
        #pragma unroll
        for (int dd = 1; dd < 16; dd <<= 1) {
            int t = __shfl_up_sync(0xFFFFFFFFu, ws, dd);
            if (lane >= dd) ws += t;
        }
        if (lane < 16) wsum[lane] = ws;
    }
    __syncthreads();
    int base = wid ? wsum[wid - 1] : 0;
    if (threadIdx.x < NBLK1) g_blk[threadIdx.x] = base + s - v;   // exclusive
}

__global__ void scan_c_kernel() {
    int gid = blockIdx.x * 256 + threadIdx.x;
    if (gid < NCELL) {
        int o = g_off[gid] + g_blk[blockIdx.x];
        g_off[gid] = o;
        g_cur[gid] = o;
    }
}

// ---------------- kernel 3: fill per-voxel point lists ----------------
__global__ void fill_kernel() {
    int p = blockIdx.x * blockDim.x + threadIdx.x;
    if (p >= NPTS) return;
    int lin = g_lin[p];
    if (lin < 0) return;
    int pos = atomicAdd(&g_cur[lin], 1);
    g_idx[pos] = p;
}

// ---------------- kernel 4: gather-sum + direct (C, cell) output ----------------
// 8 voxels per block (one per warp). Lanes 0..19 each own one float4 quad of
// the 80-channel row: one LDG.128 covers a whole 320B point row. Results land
// in a smem tile, then the block writes out[c*NCELL + v0..v0+7] as 32B
// segments — (C, cell) layout directly, no scratch, no transpose kernel.
__global__ void gather_kernel(const float4* __restrict__ x4,
                              float* __restrict__ out) {
    __shared__ float4 tile4[8][NQ];
    int wv   = threadIdx.x >> 5;          // voxel slot within block
    int lane = threadIdx.x & 31;
    int v    = blockIdx.x * 8 + wv;

    int beg = g_off[v];
    int end = g_cur[v];

    float4 acc = make_float4(0.f, 0.f, 0.f, 0.f);
    if (lane < NQ) {
        int i = beg;
        for (; i + 4 <= end; i += 4) {
            int q0 = __ldg(&g_idx[i]);
            int q1 = __ldg(&g_idx[i + 1]);
            int q2 = __ldg(&g_idx[i + 2]);
            int q3 = __ldg(&g_idx[i + 3]);
            float4 v0 = __ldg(&x4[(size_t)q0 * NQ + lane]);
            float4 v1 = __ldg(&x4[(size_t)q1 * NQ + lane]);
            float4 v2 = __ldg(&x4[(size_t)q2 * NQ + lane]);
            float4 v3 = __ldg(&x4[(size_t)q3 * NQ + lane]);
            acc.x += v0.x; acc.y += v0.y; acc.z += v0.z; acc.w += v0.w;
            acc.x += v1.x; acc.y += v1.y; acc.z += v1.z; acc.w += v1.w;
            acc.x += v2.x; acc.y += v2.y; acc.z += v2.z; acc.w += v2.w;
            acc.x += v3.x; acc.y += v3.y; acc.z += v3.z; acc.w += v3.w;
        }
        for (; i < end; i++) {
            int q = __ldg(&g_idx[i]);
            float4 vv = __ldg(&x4[(size_t)q * NQ + lane]);
            acc.x += vv.x; acc.y += vv.y; acc.z += vv.z; acc.w += vv.w;
        }
        tile4[wv][lane] = acc;
    }
    __syncthreads();

    // write 8*NC floats: thread i -> channel c = i>>3, local cell l = i&7
    const float* tf = (const float*)tile4;   // tf[l*NC + c]
    int v0 = blockIdx.x * 8;
    #pragma unroll
    for (int i = threadIdx.x; i < 8 * NC; i += 256) {
        int c = i >> 3;
        int l = i & 7;
        out[(size_t)c * NCELL + v0 + l] = tf[l * NC + c];
    }
}

// ---------------- launch ----------------
extern "C" void kernel_launch(void* const* d_in, const int* in_sizes, int n_in,
                              void* d_out, int out_size) {
    const float4* x4   = (const float4*)d_in[0];
    const int*    kept = (const int*)d_in[1];     // bool materialized as int32
    const float*  c2l  = (const float*)d_in[2];
    const float*  intr = (const float*)d_in[3];
    const float*  ida  = (const float*)d_in[4];
    const float*  bda  = (const float*)d_in[5];
    float* out = (float*)d_out;

    setup_zero_kernel<<<NBLK1, 256>>>(c2l, intr, ida, bda);
    geom_kernel<<<(NPTS + 255) / 256, 256>>>(kept);
    scan_a_kernel<<<NBLK1, 256>>>();
    scan_b_kernel<<<1, 512>>>();
    scan_c_kernel<<<NBLK1, 256>>>();
    fill_kernel<<<(NPTS + 255) / 256, 256>>>();
    gather_kernel<<<NCELL / 8, 256>>>(x4, out);
}

// round 15
// speedup vs baseline: 1.1276x; 1.1276x over previous
#include <cuda_runtime.h>
#include <cstdint>

// ---------------- problem constants (from reference) ----------------
#define FH    32
#define FW    88
#define NCAM  6
#define ND    118
#define NC    80
#define NXX   360
#define NYY   360
#define NPTS  (NCAM*ND*FH*FW)      // 1,993,728
#define NCELL (NXX*NYY)            // 129,600
#define GRID_ELEMS (NCELL*NC)      // 10,368,000 floats
#define PT_PER_CAM (ND*FH*FW)
#define PT_PER_D   (FH*FW)
#define NBLK1 507                  // ceil(NCELL/256)
#define NQ    20                   // NC/4 float4 quads per point row

// ---------------- device scratch (static: no allocation) ----------------
__device__ float g_scratch[GRID_ELEMS];   // (cell, C) accumulator
__device__ int   g_lin[NPTS];
__device__ int   g_cnt[NCELL];
__device__ int   g_off[NCELL];
__device__ int   g_cur[NCELL];
__device__ int   g_blk[512];
__device__ int   g_idx[NPTS];
// per-camera: [0:9) invPostRot [9:12) post_trans [12:21) G = E*rots*invK [21:24) E*trans+ET
__device__ float g_cam[NCAM][24];

// ---------------- exact-fp32 helpers (no FMA contraction) — FROZEN numerics ----------------
__device__ __forceinline__ float dot3(const float* m, float a, float b, float c) {
    return __fadd_rn(__fadd_rn(__fmul_rn(m[0], a), __fmul_rn(m[1], b)),
                     __fmul_rn(m[2], c));
}

__device__ __forceinline__ void inv3(const float m[9], float out[9]) {
    float a=m[0],b=m[1],c=m[2],d=m[3],e=m[4],f=m[5],g=m[6],h=m[7],i=m[8];
    float A =  (e*i - f*h);
    float B = -(d*i - f*g);
    float C =  (d*h - e*g);
    float det = a*A + b*B + c*C;
    float id = 1.0f / det;
    out[0] =  A*id;            out[1] = -(b*i - c*h)*id;  out[2] =  (b*f - c*e)*id;
    out[3] =  B*id;            out[4] =  (a*i - c*g)*id;  out[5] = -(a*f - c*d)*id;
    out[6] =  C*id;            out[7] = -(a*h - b*g)*id;  out[8] =  (a*e - b*d)*id;
}

__device__ __forceinline__ void mm3(const float A[9], const float B[9], float C[9]) {
    #pragma unroll
    for (int i = 0; i < 3; i++)
        #pragma unroll
        for (int j = 0; j < 3; j++)
            C[i*3+j] = __fadd_rn(__fadd_rn(__fmul_rn(A[i*3+0], B[0*3+j]),
                                           __fmul_rn(A[i*3+1], B[1*3+j])),
                                 __fmul_rn(A[i*3+2], B[2*3+j]));
}

// ---------------- kernel 0: setup (block 0) + zero counters (all blocks) ----------------
__global__ void setup_zero_kernel(const float* __restrict__ c2l,
                                  const float* __restrict__ intr,
                                  const float* __restrict__ ida,
                                  const float* __restrict__ bda) {
    int gid = blockIdx.x * blockDim.x + threadIdx.x;
    if (gid < NCELL) g_cnt[gid] = 0;

    if (blockIdx.x == 0 && threadIdx.x < NCAM) {
        int n = threadIdx.x;
        const float* M = c2l + n*16;
        float rots[9]  = {M[0],M[1],M[2],  M[4],M[5],M[6],  M[8],M[9],M[10]};
        float trans[3] = {M[3], M[7], M[11]};

        const float* Ki = intr + n*16;
        float K[9] = {Ki[0],Ki[1],Ki[2], Ki[4],Ki[5],Ki[6], Ki[8],Ki[9],Ki[10]};

        const float* Ai = ida + n*16;
        float PR[9] = {Ai[0],Ai[1],Ai[2], Ai[4],Ai[5],Ai[6], Ai[8],Ai[9],Ai[10]};
        float PT[3] = {Ai[3], Ai[7], Ai[11]};

        float E[9]  = {bda[0],bda[1],bda[2], bda[4],bda[5],bda[6], bda[8],bda[9],bda[10]};
        float ET[3] = {bda[3], bda[7], bda[11]};

        float invK[9], invPR[9], cmb[9], G[9];
        inv3(K, invK);
        inv3(PR, invPR);
        mm3(rots, invK, cmb);   // combine = rots @ inv(intrins)
        mm3(E, cmb, G);         // identity E -> G == cmb bit-exactly

        float o[3];
        #pragma unroll
        for (int i = 0; i < 3; i++)
            o[i] = __fadd_rn(dot3(E + i*3, trans[0], trans[1], trans[2]), ET[i]);

        float* cp = g_cam[n];
        #pragma unroll
        for (int i = 0; i < 9; i++) cp[i]      = invPR[i];
        #pragma unroll
        for (int i = 0; i < 3; i++) cp[9 + i]  = PT[i];
        #pragma unroll
        for (int i = 0; i < 9; i++) cp[12 + i] = G[i];
        #pragma unroll
        for (int i = 0; i < 3; i++) cp[21 + i] = o[i];
    }
}

// ---------------- kernel 1: geometry -> voxel index + histogram (FROZEN numerics) ----------------
__global__ void geom_kernel(const int* __restrict__ depth_kept) {
    int p = blockIdx.x * blockDim.x + threadIdx.x;
    if (p >= NPTS) return;

    int n  = p / PT_PER_CAM;
    int r  = p - n * PT_PER_CAM;
    int d  = r / PT_PER_D;
    int r2 = r - d * PT_PER_D;
    int h  = r2 / FW;
    int w  = r2 - h * FW;

    const float* cp = g_cam[n];

    const float STEPX = 703.0f / 87.0f;
    const float STEPY = 255.0f / 31.0f;
    float fx = __fmul_rn((float)w, STEPX);
    float fy = __fmul_rn((float)h, STEPY);
    float fd = __fadd_rn(1.0f, __fmul_rn(0.5f, (float)d));

    float p0 = __fadd_rn(fx, -cp[9]);
    float p1 = __fadd_rn(fy, -cp[10]);
    float p2 = __fadd_rn(fd, -cp[11]);

    float q0 = dot3(cp + 0, p0, p1, p2);
    float q1 = dot3(cp + 3, p0, p1, p2);
    float q2 = dot3(cp + 6, p0, p1, p2);

    float r0 = __fmul_rn(q0, q2);
    float r1 = __fmul_rn(q1, q2);

    float px = __fadd_rn(dot3(cp + 12, r0, r1, q2), cp[21]);
    float py = __fadd_rn(dot3(cp + 15, r0, r1, q2), cp[22]);
    float pz = __fadd_rn(dot3(cp + 18, r0, r1, q2), cp[23]);

    // XLA lowers /DX (constant) to multiply-by-RN-reciprocal — decides the
    // exact-boundary slabs (cams 0/3). Confirmed by R13 pass; do not change.
    const float INV_DXY = 1.0f / 0.3f;
    const float INV_DZ  = 1.0f / 20.0f;
    int cx = (int)floorf(__fmul_rn(__fadd_rn(px, 54.0f), INV_DXY));
    int cy = (int)floorf(__fmul_rn(__fadd_rn(py, 54.0f), INV_DXY));
    int cz = (int)floorf(__fmul_rn(__fadd_rn(pz, 10.0f), INV_DZ));

    bool ok = (cx >= 0) & (cx < NXX) & (cy >= 0) & (cy < NYY) &
              (cz >= 0) & (cz < 1)   & (depth_kept[p] != 0);

    int lin = ok ? (cx * NYY + cy) : -1;
    g_lin[p] = lin;
    if (ok) atomicAdd(&g_cnt[lin], 1);
}

// ---------------- kernels 2a/2b/2c: exclusive prefix scan (warp shuffles) ----------------
__global__ void scan_a_kernel() {
    __shared__ int wsum[8];
    int gid  = blockIdx.x * 256 + threadIdx.x;
    int lane = threadIdx.x & 31, wid = threadIdx.x >> 5;
    int v = (gid < NCELL) ? g_cnt[gid] : 0;
    int s = v;
    #pragma unroll
    for (int dd = 1; dd < 32; dd <<= 1) {
        int t = __shfl_up_sync(0xFFFFFFFFu, s, dd);
        if (lane >= dd) s += t;
    }
    if (lane == 31) wsum[wid] = s;
    __syncthreads();
    if (wid == 0) {
        int ws = (lane < 8) ? wsum[lane] : 0;
        #pragma unroll
        for (int dd = 1; dd < 8; dd <<= 1) {
            int t = __shfl_up_sync(0xFFFFFFFFu, ws, dd);
            if (lane >= dd) ws += t;
        }
        if (lane < 8) wsum[lane] = ws;   // inclusive warp-prefix
    }
    __syncthreads();
    int base = wid ? wsum[wid - 1] : 0;
    if (gid < NCELL) g_off[gid] = base + s - v;
    if (threadIdx.x == 255) g_blk[blockIdx.x] = base + s;   // block total
}

__global__ void scan_b_kernel() {
    __shared__ int wsum[16];
    int lane = threadIdx.x & 31, wid = threadIdx.x >> 5;
    int v = (threadIdx.x < NBLK1) ? g_blk[threadIdx.x] : 0;
    int s = v;
    #pragma unroll
    for (int dd = 1; dd < 32; dd <<= 1) {
        int t = __shfl_up_sync(0xFFFFFFFFu, s, dd);
        if (lane >= dd) s += t;
    }
    if (lane == 31) wsum[wid] = s;
    __syncthreads();
    if (wid == 0) {
        int ws = (lane < 16) ? wsum[lane] : 0;
        #pragma unroll
        for (int dd = 1; dd < 16; dd <<= 1) {
            int t = __shfl_up_sync(0xFFFFFFFFu, ws, dd);
            if (lane >= dd) ws += t;
        }
        if (lane < 16) wsum[lane] = ws;
    }
    __syncthreads();
    int base = wid ? wsum[wid - 1] : 0;
    if (threadIdx.x < NBLK1) g_blk[threadIdx.x] = base + s - v;   // exclusive
}

__global__ void scan_c_kernel() {
    int gid = blockIdx.x * 256 + threadIdx.x;
    if (gid < NCELL) {
        int o = g_off[gid] + g_blk[blockIdx.x];
        g_off[gid] = o;
        g_cur[gid] = o;
    }
}

// ---------------- kernel 3: fill per-voxel point lists ----------------
__global__ void fill_kernel() {
    int p = blockIdx.x * blockDim.x + threadIdx.x;
    if (p >= NPTS) return;
    int lin = g_lin[p];
    if (lin < 0) return;
    int pos = atomicAdd(&g_cur[lin], 1);
    g_idx[pos] = p;
}

// ---------------- kernel 4: gather-sum, warp-per-voxel, float4, MLP=8 ----------------
// Barrier-free (R13 topology): each warp owns one voxel, retires independently.
// Lanes 0..19 own one float4 quad of the 80-ch row: 1 LDG.128/point (vs 3
// LDG.32 in R13), unrolled 8 deep -> 8 in-flight 128-bit loads per warp.
// Accumulator written once as a coalesced 320B float4 store to scratch.
__global__ void gather_kernel(const float4* __restrict__ x4) {
    int warp = (blockIdx.x * blockDim.x + threadIdx.x) >> 5;
    int lane = threadIdx.x & 31;
    if (warp >= NCELL || lane >= NQ) return;

    int beg = g_off[warp];
    int end = g_cur[warp];

    float4 acc = make_float4(0.f, 0.f, 0.f, 0.f);
    int i = beg;
    for (; i + 8 <= end; i += 8) {
        int q0 = __ldg(&g_idx[i]);
        int q1 = __ldg(&g_idx[i + 1]);
        int q2 = __ldg(&g_idx[i + 2]);
        int q3 = __ldg(&g_idx[i + 3]);
        int q4 = __ldg(&g_idx[i + 4]);
        int q5 = __ldg(&g_idx[i + 5]);
        int q6 = __ldg(&g_idx[i + 6]);
        int q7 = __ldg(&g_idx[i + 7]);
        float4 v0 = __ldg(&x4[(size_t)q0 * NQ + lane]);
        float4 v1 = __ldg(&x4[(size_t)q1 * NQ + lane]);
        float4 v2 = __ldg(&x4[(size_t)q2 * NQ + lane]);
        float4 v3 = __ldg(&x4[(size_t)q3 * NQ + lane]);
        float4 v4 = __ldg(&x4[(size_t)q4 * NQ + lane]);
        float4 v5 = __ldg(&x4[(size_t)q5 * NQ + lane]);
        float4 v6 = __ldg(&x4[(size_t)q6 * NQ + lane]);
        float4 v7 = __ldg(&x4[(size_t)q7 * NQ + lane]);
        acc.x += v0.x; acc.y += v0.y; acc.z += v0.z; acc.w += v0.w;
        acc.x += v1.x; acc.y += v1.y; acc.z += v1.z; acc.w += v1.w;
        acc.x += v2.x; acc.y += v2.y; acc.z += v2.z; acc.w += v2.w;
        acc.x += v3.x; acc.y += v3.y; acc.z += v3.z; acc.w += v3.w;
        acc.x += v4.x; acc.y += v4.y; acc.z += v4.z; acc.w += v4.w;
        acc.x += v5.x; acc.y += v5.y; acc.z += v5.z; acc.w += v5.w;
        acc.x += v6.x; acc.y += v6.y; acc.z += v6.z; acc.w += v6.w;
        acc.x += v7.x; acc.y += v7.y; acc.z += v7.z; acc.w += v7.w;
    }
    for (; i < end; i++) {
        int q = __ldg(&g_idx[i]);
        float4 vv = __ldg(&x4[(size_t)q * NQ + lane]);
        acc.x += vv.x; acc.y += vv.y; acc.z += vv.z; acc.w += vv.w;
    }

    reinterpret_cast<float4*>(g_scratch)[(size_t)warp * NQ + lane] = acc;
}

// ---------------- kernel 5: (cell, C) -> (C, cell) transpose into output ----------------
__global__ void transpose_kernel(float* __restrict__ out) {
    __shared__ float tile[32][NC + 1];
    int lin0 = blockIdx.x * 32;

    for (int i = threadIdx.x; i < 32 * NC; i += blockDim.x) {
        int l = i / NC;
        int c = i - l * NC;
        tile[l][c] = g_scratch[(size_t)(lin0 + l) * NC + c];
    }
    __syncthreads();
    for (int i = threadIdx.x; i < 32 * NC; i += blockDim.x) {
        int c = i / 32;
        int l = i - c * 32;
        out[(size_t)c * NCELL + lin0 + l] = tile[l][c];
    }
}

// ---------------- launch ----------------
extern "C" void kernel_launch(void* const* d_in, const int* in_sizes, int n_in,
                              void* d_out, int out_size) {
    const float4* x4   = (const float4*)d_in[0];
    const int*    kept = (const int*)d_in[1];     // bool materialized as int32
    const float*  c2l  = (const float*)d_in[2];
    const float*  intr = (const float*)d_in[3];
    const float*  ida  = (const float*)d_in[4];
    const float*  bda  = (const float*)d_in[5];
    float* out = (float*)d_out;

    setup_zero_kernel<<<NBLK1, 256>>>(c2l, intr, ida, bda);
    geom_kernel<<<(NPTS + 255) / 256, 256>>>(kept);
    scan_a_kernel<<<NBLK1, 256>>>();
    scan_b_kernel<<<1, 512>>>();
    scan_c_kernel<<<NBLK1, 256>>>();
    fill_kernel<<<(NPTS + 255) / 256, 256>>>();
    gather_kernel<<<NCELL / 8, 256>>>(x4);
    transpose_kernel<<<NCELL / 32, 256>>>(out);
}

// round 17
// speedup vs baseline: 1.4056x; 1.2465x over previous
#include <cuda_runtime.h>
#include <cstdint>

// ---------------- problem constants (from reference) ----------------
#define FH    32
#define FW    88
#define NCAM  6
#define ND    118
#define NC    80
#define NXX   360
#define NYY   360
#define NPTS  (NCAM*ND*FH*FW)      // 1,993,728
#define NCELL (NXX*NYY)            // 129,600
#define GRID_ELEMS (NCELL*NC)      // 10,368,000 floats (41.5 MB, L2-resident)
#define PT_PER_CAM (ND*FH*FW)
#define PT_PER_D   (FH*FW)
#define NQ    20                   // NC/4 float4 quads per point row
#define QUADS (NPTS*NQ)            // 39,874,560 scatter work items

// ---------------- device scratch (static: no allocation) ----------------
__device__ float g_scratch[GRID_ELEMS];   // (cell, C) accumulator — lives in L2
__device__ int   g_lin[NPTS];             // voxel index per point, -1 if dropped
// per-camera: [0:9) invPostRot [9:12) post_trans [12:21) G = E*rots*invK [21:24) E*trans+ET
__device__ float g_cam[NCAM][24];

// ---------------- exact-fp32 helpers (no FMA contraction) — FROZEN numerics ----------------
__device__ __forceinline__ float dot3(const float* m, float a, float b, float c) {
    return __fadd_rn(__fadd_rn(__fmul_rn(m[0], a), __fmul_rn(m[1], b)),
                     __fmul_rn(m[2], c));
}

__device__ __forceinline__ void inv3(const float m[9], float out[9]) {
    float a=m[0],b=m[1],c=m[2],d=m[3],e=m[4],f=m[5],g=m[6],h=m[7],i=m[8];
    float A =  (e*i - f*h);
    float B = -(d*i - f*g);
    float C =  (d*h - e*g);
    float det = a*A + b*B + c*C;
    float id = 1.0f / det;
    out[0] =  A*id;            out[1] = -(b*i - c*h)*id;  out[2] =  (b*f - c*e)*id;
    out[3] =  B*id;            out[4] =  (a*i - c*g)*id;  out[5] = -(a*f - c*d)*id;
    out[6] =  C*id;            out[7] = -(a*h - b*g)*id;  out[8] =  (a*e - b*d)*id;
}

__device__ __forceinline__ void mm3(const float A[9], const float B[9], float C[9]) {
    #pragma unroll
    for (int i = 0; i < 3; i++)
        #pragma unroll
        for (int j = 0; j < 3; j++)
            C[i*3+j] = __fadd_rn(__fadd_rn(__fmul_rn(A[i*3+0], B[0*3+j]),
                                           __fmul_rn(A[i*3+1], B[1*3+j])),
                                 __fmul_rn(A[i*3+2], B[2*3+j]));
}

// ---------------- kernel 0: zero scratch (all blocks) + camera setup (block 0) ----------------
__global__ void zero_setup_kernel(const float* __restrict__ c2l,
                                  const float* __restrict__ intr,
                                  const float* __restrict__ ida,
                                  const float* __restrict__ bda) {
    int gid = blockIdx.x * blockDim.x + threadIdx.x;
    if (gid < GRID_ELEMS / 4)
        reinterpret_cast<float4*>(g_scratch)[gid] = make_float4(0.f, 0.f, 0.f, 0.f);

    if (blockIdx.x == 0 && threadIdx.x < NCAM) {
        int n = threadIdx.x;
        const float* M = c2l + n*16;
        float rots[9]  = {M[0],M[1],M[2],  M[4],M[5],M[6],  M[8],M[9],M[10]};
        float trans[3] = {M[3], M[7], M[11]};

        const float* Ki = intr + n*16;
        float K[9] = {Ki[0],Ki[1],Ki[2], Ki[4],Ki[5],Ki[6], Ki[8],Ki[9],Ki[10]};

        const float* Ai = ida + n*16;
        float PR[9] = {Ai[0],Ai[1],Ai[2], Ai[4],Ai[5],Ai[6], Ai[8],Ai[9],Ai[10]};
        float PT[3] = {Ai[3], Ai[7], Ai[11]};

        float E[9]  = {bda[0],bda[1],bda[2], bda[4],bda[5],bda[6], bda[8],bda[9],bda[10]};
        float ET[3] = {bda[3], bda[7], bda[11]};

        float invK[9], invPR[9], cmb[9], G[9];
        inv3(K, invK);
        inv3(PR, invPR);
        mm3(rots, invK, cmb);   // combine = rots @ inv(intrins)
        mm3(E, cmb, G);         // identity E -> G == cmb bit-exactly

        float o[3];
        #pragma unroll
        for (int i = 0; i < 3; i++)
            o[i] = __fadd_rn(dot3(E + i*3, trans[0], trans[1], trans[2]), ET[i]);

        float* cp = g_cam[n];
        #pragma unroll
        for (int i = 0; i < 9; i++) cp[i]      = invPR[i];
        #pragma unroll
        for (int i = 0; i < 3; i++) cp[9 + i]  = PT[i];
        #pragma unroll
        for (int i = 0; i < 9; i++) cp[12 + i] = G[i];
        #pragma unroll
        for (int i = 0; i < 3; i++) cp[21 + i] = o[i];
    }
}

// ---------------- kernel 1: geometry -> voxel index (FROZEN numerics, R13-verified) ----------------
__global__ void geom_kernel(const int* __restrict__ depth_kept) {
    int p = blockIdx.x * blockDim.x + threadIdx.x;
    if (p >= NPTS) return;

    int n  = p / PT_PER_CAM;
    int r  = p - n * PT_PER_CAM;
    int d  = r / PT_PER_D;
    int r2 = r - d * PT_PER_D;
    int h  = r2 / FW;
    int w  = r2 - h * FW;

    const float* cp = g_cam[n];

    const float STEPX = 703.0f / 87.0f;
    const float STEPY = 255.0f / 31.0f;
    float fx = __fmul_rn((float)w, STEPX);
    float fy = __fmul_rn((float)h, STEPY);
    float fd = __fadd_rn(1.0f, __fmul_rn(0.5f, (float)d));

    float p0 = __fadd_rn(fx, -cp[9]);
    float p1 = __fadd_rn(fy, -cp[10]);
    float p2 = __fadd_rn(fd, -cp[11]);

    float q0 = dot3(cp + 0, p0, p1, p2);
    float q1 = dot3(cp + 3, p0, p1, p2);
    float q2 = dot3(cp + 6, p0, p1, p2);

    float r0 = __fmul_rn(q0, q2);
    float r1 = __fmul_rn(q1, q2);

    float px = __fadd_rn(dot3(cp + 12, r0, r1, q2), cp[21]);
    float py = __fadd_rn(dot3(cp + 15, r0, r1, q2), cp[22]);
    float pz = __fadd_rn(dot3(cp + 18, r0, r1, q2), cp[23]);

    // XLA lowers /DX (constant) to multiply-by-RN-reciprocal — decides the
    // exact-boundary slabs (cams 0/3). Confirmed by R13 pass; do not change.
    const float INV_DXY = 1.0f / 0.3f;
    const float INV_DZ  = 1.0f / 20.0f;
    int cx = (int)floorf(__fmul_rn(__fadd_rn(px, 54.0f), INV_DXY));
    int cy = (int)floorf(__fmul_rn(__fadd_rn(py, 54.0f), INV_DXY));
    int cz = (int)floorf(__fmul_rn(__fadd_rn(pz, 10.0f), INV_DZ));

    bool ok = (cx >= 0) & (cx < NXX) & (cy >= 0) & (cy < NYY) &
              (cz >= 0) & (cz < 1)   & (depth_kept[p] != 0);

    g_lin[p] = ok ? (cx * NYY + cy) : -1;
}

// ---------------- kernel 2: streaming scatter (red.v4 into L2-resident scratch) ----------------
// Thread per (point, quad): x read is perfectly coalesced & streamed exactly
// once per KEPT point (lin checked before the x load issues — dropped rows
// never touch DRAM). The 41.5MB accumulator stays L2-resident, so the RMW
// traffic never reaches HBM. No histogram/scan/fill passes at all.
__global__ void scatter_kernel(const float4* __restrict__ x4) {
    int idx = blockIdx.x * blockDim.x + threadIdx.x;
    if (idx >= QUADS) return;

    int p = idx / NQ;            // point index  (broadcast g_lin hit per 20 lanes)
    int q = idx - p * NQ;        // channel quad 0..19

    int lin = __ldg(&g_lin[p]);
    if (lin < 0) return;

    float4 v = __ldg(&x4[idx]);  // coalesced stream of x
    float* dst = g_scratch + (size_t)lin * NC + q * 4;
    asm volatile("red.global.add.v4.f32 [%0], {%1, %2, %3, %4};"
                 :: "l"(dst), "f"(v.x), "f"(v.y), "f"(v.z), "f"(v.w)
                 : "memory");
}

// ---------------- kernel 3: (cell, C) -> (C, cell) transpose into output ----------------
__global__ void transpose_kernel(float* __restrict__ out) {
    __shared__ float tile[32][NC + 1];
    int lin0 = blockIdx.x * 32;

    for (int i = threadIdx.x; i < 32 * NC; i += blockDim.x) {
        int l = i / NC;
        int c = i - l * NC;
        tile[l][c] = g_scratch[(size_t)(lin0 + l) * NC + c];
    }
    __syncthreads();
    for (int i = threadIdx.x; i < 32 * NC; i += blockDim.x) {
        int c = i / 32;
        int l = i - c * 32;
        out[(size_t)c * NCELL + lin0 + l] = tile[l][c];
    }
}

// ---------------- launch: 4 kernels, minimal ladder ----------------
extern "C" void kernel_launch(void* const* d_in, const int* in_sizes, int n_in,
                              void* d_out, int out_size) {
    const float4* x4   = (const float4*)d_in[0];
    const int*    kept = (const int*)d_in[1];     // bool materialized as int32
    const float*  c2l  = (const float*)d_in[2];
    const float*  intr = (const float*)d_in[3];
    const float*  ida  = (const float*)d_in[4];
    const float*  bda  = (const float*)d_in[5];
    float* out = (float*)d_out;

    zero_setup_kernel<<<(GRID_ELEMS/4 + 255) / 256, 256>>>(c2l, intr, ida, bda);
    geom_kernel<<<(NPTS + 255) / 256, 256>>>(kept);
    scatter_kernel<<<(QUADS + 255) / 256, 256>>>(x4);
    transpose_kernel<<<NCELL / 32, 256>>>(out);
}